// round 14
// baseline (speedup 1.0000x reference)
#include <cuda_runtime.h>
#include <cstdint>

// Problem constants (fixed by the reference).
#define Bsz   1024
#define Lsz   32
#define Hsz   128
#define Gsz   8      // samples per CTA
#define G2sz  4      // sample pairs per CTA
#define NCTA  128    // Bsz / Gsz
#define TPB   512    // 4 k-quarters x 128 output lanes
#define NQ    4
#define KQ    (Hsz / NQ)   // 32 k-values per quarter

// Vertical-carry scratch: [cta][g2][lattice p][layer][t] as float2 (sample pair).
__device__ float2 g_scr[(size_t)NCTA * G2sz * Lsz * 2 * Hsz];

static __device__ __forceinline__ unsigned long long pk2(float x, float y) {
    unsigned long long r;
    asm("mov.b64 %0, {%1, %2};" : "=l"(r) : "f"(x), "f"(y));
    return r;
}
static __device__ __forceinline__ float2 up2(unsigned long long v) {
    float2 r;
    asm("mov.b64 {%0, %1}, %2;" : "=f"(r.x), "=f"(r.y) : "l"(v));
    return r;
}
// packed fp32x2 FMA / ADD (FFMA2 in SASS — PTX-only path on sm_103a)
static __device__ __forceinline__ unsigned long long fma2(unsigned long long a,
                                                          unsigned long long b,
                                                          unsigned long long c) {
    unsigned long long d;
    asm("fma.rn.f32x2 %0, %1, %2, %3;" : "=l"(d) : "l"(a), "l"(b), "l"(c));
    return d;
}
static __device__ __forceinline__ unsigned long long add2(unsigned long long a,
                                                          unsigned long long b) {
    unsigned long long d;
    asm("add.rn.f32x2 %0, %1, %2;" : "=l"(d) : "l"(a), "l"(b));
    return d;
}
static __device__ __forceinline__ float eluf(float v) {
    return v > 0.f ? v : (__expf(v) - 1.f);
}

__global__ void __launch_bounds__(TPB, 1)
rnn2d_kernel(const int* __restrict__ x,
             const float* __restrict__ WH,
             const float* __restrict__ WV,
             const float* __restrict__ WS0,
             const float* __restrict__ WS1,
             const float* __restrict__ Wout,
             const float* __restrict__ bout,
             float* __restrict__ out)
{
    // Carry operand arrays: .x = {carryH pair}, .y = {carryV pair} packed fp32x2.
    __shared__ ulonglong2 C0s[G2sz][Hsz];              // layer-0 carries
    __shared__ ulonglong2 C1s[G2sz][Hsz];              // layer-1 carries
    __shared__ unsigned long long H0sm[G2sz][Hsz];     // current-site h0 pairs
    __shared__ unsigned long long RedS[NQ - 1][G2sz][Hsz]; // quarter partials
    __shared__ float2 OutRedS[4][G2sz];                // per-warp output-dot partials
    __shared__ float WS0s[4 * Hsz];
    __shared__ float WoutS[Hsz];
    __shared__ int   xbuf[2][Gsz][Lsz];                // current / previous lattice rows
    __shared__ float boutS;

    const int tid = threadIdx.x;
    const int cta = blockIdx.x;
    const int t   = tid & (Hsz - 1);    // output lane 0..127
    const int q   = tid >> 7;           // k-quarter 0..3
    const int k0  = q * KQ;

    // staging assignment: quarter q stages layer (q>>1) for pair-group base 2*(q&1)
    const int stgL  = q >> 1;
    const int stgPb = (q & 1) * 2;

    for (int idx = tid; idx < 4 * Hsz; idx += TPB) WS0s[idx] = WS0[idx];
    for (int idx = tid; idx < Hsz; idx += TPB)     WoutS[idx] = Wout[idx];
    if (tid == 0) boutS = bout[0];

    const float* WH0 = WH;
    const float* WH1 = WH + Hsz * Hsz;
    const float* WV0 = WV;
    const float* WV1 = WV + Hsz * Hsz;

    float2* scrBase = g_scr + (size_t)cta * (G2sz * Lsz * 2 * Hsz);

    float lpAcc = 0.f;
    float2 vpref[2] = {{0.f, 0.f}, {0.f, 0.f}};
    __syncthreads();

    for (int i = 0; i < Lsz; ++i) {
        const int d = (i & 1) ? -1 : 1;               // boustrophedon direction
        const int cur = i & 1, prv = cur ^ 1;

        // stage the whole lattice row into smem (coalesced, once per row)
        if (tid < Gsz * Lsz) {
            const int g = tid >> 5, c = tid & 31;
            xbuf[cur][g][c] = x[((cta * Gsz + g) * Lsz + i) * Lsz + c];
        }

        for (int j = 0; j < Lsz; ++j) {
            const int p = (d == 1) ? j : (Lsz - 1 - j);    // lattice column

            // ---------------- staging ----------------
            if (j == 0) {                     // no prefetch for the row's first column
                if (i > 0) {
#pragma unroll
                    for (int e = 0; e < 2; ++e)
                        vpref[e] = scrBase[(((stgPb + e) * Lsz + p) * 2 + stgL) * Hsz + t];
                } else {
                    vpref[0] = make_float2(0.f, 0.f);
                    vpref[1] = make_float2(0.f, 0.f);
                }
            }
            {
                ulonglong2* Cb = stgL ? &C1s[0][0] : &C0s[0][0];
#pragma unroll
                for (int e = 0; e < 2; ++e) {
                    ulonglong2* Cp = Cb + (stgPb + e) * Hsz + t;
                    Cp->y = pk2(vpref[e].x, vpref[e].y);
                    if (j == 0) Cp->x = 0ull;             // horizontal carry resets per row
                }
            }
            __syncthreads();   // s1

            // prefetch next column's vertical carries (hidden under compute)
            if (j < Lsz - 1) {
                const int pn = p + d;
                if (i > 0) {
#pragma unroll
                    for (int e = 0; e < 2; ++e)
                        vpref[e] = scrBase[(((stgPb + e) * Lsz + pn) * 2 + stgL) * Hsz + t];
                } else {
                    vpref[0] = make_float2(0.f, 0.f);
                    vpref[1] = make_float2(0.f, 0.f);
                }
            }

            // ---------------- layer 0 ----------------
            unsigned long long a[G2sz];
#pragma unroll
            for (int g2 = 0; g2 < G2sz; ++g2) a[g2] = 0ull;
            {
                const float* pwh = WH0 + (size_t)k0 * Hsz + t;
                const float* pwv = WV0 + (size_t)k0 * Hsz + t;
#pragma unroll 8
                for (int kk = 0; kk < KQ; ++kk) {
                    const int k = k0 + kk;
                    const float whf = __ldg(pwh); pwh += Hsz;
                    const float wvf = __ldg(pwv); pwv += Hsz;
                    const unsigned long long wh = pk2(whf, whf);
                    const unsigned long long wv = pk2(wvf, wvf);
#pragma unroll
                    for (int g2 = 0; g2 < G2sz; ++g2) {
                        const ulonglong2 c = C0s[g2][k];   // LDS.128 broadcast
                        a[g2] = fma2(c.x, wh, a[g2]);
                        a[g2] = fma2(c.y, wv, a[g2]);
                    }
                }
            }
            if (q) {
#pragma unroll
                for (int g2 = 0; g2 < G2sz; ++g2) RedS[q - 1][g2][t] = a[g2];
            }
            __syncthreads();   // s2
            if (!q) {
#pragma unroll
                for (int g2 = 0; g2 < G2sz; ++g2) {
                    const unsigned long long s =
                        add2(add2(a[g2], RedS[0][g2][t]),
                             add2(RedS[1][g2][t], RedS[2][g2][t]));
                    float2 h = up2(s);
                    // one-hot state term: at most two row-picks of WS0
                    const int he = (j > 0) ? xbuf[cur][2 * g2][p - d] : -1;
                    const int ho = (j > 0) ? xbuf[cur][2 * g2 + 1][p - d] : -1;
                    const int ve = (i > 0) ? xbuf[prv][2 * g2][p] : -1;
                    const int vo = (i > 0) ? xbuf[prv][2 * g2 + 1][p] : -1;
                    if (he >= 0) h.x += WS0s[he * Hsz + t];
                    if (ve >= 0) h.x += WS0s[(2 + ve) * Hsz + t];
                    if (ho >= 0) h.y += WS0s[ho * Hsz + t];
                    if (vo >= 0) h.y += WS0s[(2 + vo) * Hsz + t];
                    h.x = eluf(h.x); h.y = eluf(h.y);
                    const unsigned long long hu = pk2(h.x, h.y);
                    C0s[g2][t].x = hu;                                   // next-site carryH0
                    H0sm[g2][t] = hu;                                    // feeds WS1 matvec
                    scrBase[((g2 * Lsz + p) * 2 + 0) * Hsz + t] = h;     // next-row carryV0
                }
            }
            __syncthreads();   // s3

            // ---------------- layer 1 ----------------
#pragma unroll
            for (int g2 = 0; g2 < G2sz; ++g2) a[g2] = 0ull;
            {
                const float* pwh = WH1 + (size_t)k0 * Hsz + t;
                const float* pwv = WV1 + (size_t)k0 * Hsz + t;
                const float* pws = WS1 + (size_t)k0 * Hsz + t;
#pragma unroll 8
                for (int kk = 0; kk < KQ; ++kk) {
                    const int k = k0 + kk;
                    const float whf = __ldg(pwh); pwh += Hsz;
                    const float wvf = __ldg(pwv); pwv += Hsz;
                    const float wsf = __ldg(pws); pws += Hsz;
                    const unsigned long long wh = pk2(whf, whf);
                    const unsigned long long wv = pk2(wvf, wvf);
                    const unsigned long long ws = pk2(wsf, wsf);
#pragma unroll
                    for (int g2 = 0; g2 < G2sz; ++g2) {
                        const ulonglong2 c = C1s[g2][k];
                        const unsigned long long h0u = H0sm[g2][k];
                        a[g2] = fma2(c.x, wh, a[g2]);
                        a[g2] = fma2(c.y, wv, a[g2]);
                        a[g2] = fma2(h0u, ws, a[g2]);
                    }
                }
            }
            if (q) {
#pragma unroll
                for (int g2 = 0; g2 < G2sz; ++g2) RedS[q - 1][g2][t] = a[g2];
            }
            __syncthreads();   // s4
            if (!q) {
                const float wof = WoutS[t];
                const unsigned long long wo = pk2(wof, wof);
#pragma unroll
                for (int g2 = 0; g2 < G2sz; ++g2) {
                    const unsigned long long s =
                        add2(add2(a[g2], RedS[0][g2][t]),
                             add2(RedS[1][g2][t], RedS[2][g2][t]));
                    float2 h = up2(s);
                    h.x = eluf(h.x); h.y = eluf(h.y);
                    const unsigned long long hu = pk2(h.x, h.y);
                    C1s[g2][t].x = hu;                                   // next-site carryH1
                    scrBase[((g2 * Lsz + p) * 2 + 1) * Hsz + t] = h;     // next-row carryV1
                    a[g2] = fma2(hu, wo, 0ull);                          // output-dot partial
                }
                // intra-warp reduce of the output dot (pairs stay packed)
#pragma unroll
                for (int off = 16; off > 0; off >>= 1) {
#pragma unroll
                    for (int g2 = 0; g2 < G2sz; ++g2)
                        a[g2] = add2(a[g2], __shfl_down_sync(0xffffffffu, a[g2], off));
                }
                if ((tid & 31) == 0) {
#pragma unroll
                    for (int g2 = 0; g2 < G2sz; ++g2)
                        OutRedS[tid >> 5][g2] = up2(a[g2]);
                }
            }
            __syncthreads();   // s5
            if (tid < Gsz) {
                const int g = tid;
                float c = boutS;
#pragma unroll
                for (int w = 0; w < 4; ++w) {
                    const float2 v = OutRedS[w][g >> 1];
                    c += (g & 1) ? v.y : v.x;
                }
                // 0.5 * log_softmax([0, c]) picked by the observed spin
                const float sp = fmaxf(c, 0.f) + log1pf(__expf(-fabsf(c)));
                float lp = 0.5f * (((xbuf[cur][g][p] == 1) ? c : 0.f) - sp);
                if (!(lp == lp)) lp = -35.0f;   // nan_to_num semantics
                lpAcc += lp;
            }
        }
    }

    if (tid < Gsz) out[cta * Gsz + tid] = lpAcc;
}

extern "C" void kernel_launch(void* const* d_in, const int* in_sizes, int n_in,
                              void* d_out, int out_size) {
    const int*   x    = (const int*)d_in[0];
    const float* WH   = (const float*)d_in[1];
    const float* WV   = (const float*)d_in[2];
    const float* WS0  = (const float*)d_in[3];
    const float* WS1  = (const float*)d_in[4];
    const float* Wout = (const float*)d_in[5];
    const float* bo   = (const float*)d_in[6];
    float* out = (float*)d_out;
    rnn2d_kernel<<<NCTA, TPB>>>(x, WH, WV, WS0, WS1, Wout, bo, out);
}

// round 15
// speedup vs baseline: 1.4397x; 1.4397x over previous
#include <cuda_runtime.h>
#include <cstdint>

// Problem constants (fixed by the reference).
#define Bsz   1024
#define Lsz   32
#define Hsz   128
#define Gsz   8      // samples per CTA
#define G2sz  4      // sample pairs per CTA
#define NCTA  128    // Bsz / Gsz
#define TPB   512
#define NQ    16     // k-groups
#define KQ    8      // k-values per group (NQ*KQ = 128)

// Vertical-carry scratch: [cta][g2][lattice p][layer][t] as float2 (sample pair).
__device__ float2 g_scr[(size_t)NCTA * G2sz * Lsz * 2 * Hsz];

static __device__ __forceinline__ unsigned long long pk2(float x, float y) {
    unsigned long long r;
    asm("mov.b64 %0, {%1, %2};" : "=l"(r) : "f"(x), "f"(y));
    return r;
}
static __device__ __forceinline__ float2 up2(unsigned long long v) {
    float2 r;
    asm("mov.b64 {%0, %1}, %2;" : "=f"(r.x), "=f"(r.y) : "l"(v));
    return r;
}
// packed fp32x2 FMA / ADD (FFMA2 in SASS — PTX-only path on sm_103a)
static __device__ __forceinline__ unsigned long long fma2(unsigned long long a,
                                                          unsigned long long b,
                                                          unsigned long long c) {
    unsigned long long d;
    asm("fma.rn.f32x2 %0, %1, %2, %3;" : "=l"(d) : "l"(a), "l"(b), "l"(c));
    return d;
}
static __device__ __forceinline__ unsigned long long add2(unsigned long long a,
                                                          unsigned long long b) {
    unsigned long long d;
    asm("add.rn.f32x2 %0, %1, %2;" : "=l"(d) : "l"(a), "l"(b));
    return d;
}
static __device__ __forceinline__ float eluf(float v) {
    return v > 0.f ? v : (__expf(v) - 1.f);
}

__global__ void __launch_bounds__(TPB, 1)
rnn2d_kernel(const int* __restrict__ x,
             const float* __restrict__ WH,
             const float* __restrict__ WV,
             const float* __restrict__ WS0,
             const float* __restrict__ WS1,
             const float* __restrict__ Wout,
             const float* __restrict__ bout,
             float* __restrict__ out)
{
    // Carry operand arrays: .x = {carryH pair}, .y = {carryV pair} packed fp32x2.
    __shared__ ulonglong2 C0s[G2sz][Hsz];                 // layer-0 carries
    __shared__ ulonglong2 C1s[G2sz][Hsz];                 // layer-1 carries
    __shared__ unsigned long long H0sm[G2sz][Hsz];        // current-site h0 pairs
    __shared__ unsigned long long RedS[G2sz][NQ][Hsz];    // k-group partials (64 KB)
    __shared__ float2 OutRedS[16];                        // per-warp output-dot partials
    __shared__ float WS0s[4 * Hsz];
    __shared__ float WoutS[Hsz];
    __shared__ int   xbuf[2][Gsz][Lsz];                   // current / previous lattice rows
    __shared__ float boutS;

    const int tid = threadIdx.x;
    const int cta = blockIdx.x;

    // matvec role: thread owns outputs {t4, t4+32, t4+64, t4+96} for k in [kbase, kbase+KQ)
    const int t4    = tid & 31;
    const int q     = tid >> 5;          // k-group 0..15 (= warp id)
    const int kbase = q * KQ;

    // combine role: one output (cg, ct) per thread
    const int ct = tid & 127;
    const int cg = tid >> 7;             // 0..3

    // staging role: group cg stages layer (cg>>1) for pair-base 2*(cg&1)
    const int stgL  = cg >> 1;
    const int stgPb = (cg & 1) * 2;

    for (int idx = tid; idx < 4 * Hsz; idx += TPB) WS0s[idx] = WS0[idx];
    for (int idx = tid; idx < Hsz; idx += TPB)     WoutS[idx] = Wout[idx];
    if (tid == 0) boutS = bout[0];

    const float* WH0 = WH;
    const float* WH1 = WH + Hsz * Hsz;
    const float* WV0 = WV;
    const float* WV1 = WV + Hsz * Hsz;

    float2* scrBase = g_scr + (size_t)cta * (G2sz * Lsz * 2 * Hsz);

    float lpAcc = 0.f;
    float2 vpref[2] = {{0.f, 0.f}, {0.f, 0.f}};
    __syncthreads();

    for (int i = 0; i < Lsz; ++i) {
        const int d = (i & 1) ? -1 : 1;               // boustrophedon direction
        const int cur = i & 1, prv = cur ^ 1;

        // stage the whole lattice row into smem (coalesced, once per row)
        if (tid < Gsz * Lsz) {
            const int g = tid >> 5, c = tid & 31;
            xbuf[cur][g][c] = x[((cta * Gsz + g) * Lsz + i) * Lsz + c];
        }

        for (int j = 0; j < Lsz; ++j) {
            const int p = (d == 1) ? j : (Lsz - 1 - j);    // lattice column

            // ---------------- staging ----------------
            if (j == 0) {                     // no prefetch available for first column
                if (i > 0) {
#pragma unroll
                    for (int e = 0; e < 2; ++e)
                        vpref[e] = scrBase[(((stgPb + e) * Lsz + p) * 2 + stgL) * Hsz + ct];
                } else {
                    vpref[0] = make_float2(0.f, 0.f);
                    vpref[1] = make_float2(0.f, 0.f);
                }
            }
            {
                ulonglong2* Cb = stgL ? &C1s[0][0] : &C0s[0][0];
#pragma unroll
                for (int e = 0; e < 2; ++e) {
                    ulonglong2* Cp = Cb + (stgPb + e) * Hsz + ct;
                    Cp->y = pk2(vpref[e].x, vpref[e].y);
                    if (j == 0) Cp->x = 0ull;             // horizontal carry resets per row
                }
            }
            __syncthreads();   // s1

            // prefetch next column's vertical carries (hidden under compute)
            if (j < Lsz - 1) {
                const int pn = p + d;
                if (i > 0) {
#pragma unroll
                    for (int e = 0; e < 2; ++e)
                        vpref[e] = scrBase[(((stgPb + e) * Lsz + pn) * 2 + stgL) * Hsz + ct];
                } else {
                    vpref[0] = make_float2(0.f, 0.f);
                    vpref[1] = make_float2(0.f, 0.f);
                }
            }

            // ---------------- layer 0 matvec ----------------
            unsigned long long a[G2sz][4];
#pragma unroll
            for (int g2 = 0; g2 < G2sz; ++g2)
#pragma unroll
                for (int m = 0; m < 4; ++m) a[g2][m] = 0ull;
            {
                const float* pwh = WH0 + (size_t)kbase * Hsz + t4;
                const float* pwv = WV0 + (size_t)kbase * Hsz + t4;
#pragma unroll 4
                for (int kk = 0; kk < KQ; ++kk) {
                    const int k = kbase + kk;
                    unsigned long long whp[4], wvp[4];
#pragma unroll
                    for (int m = 0; m < 4; ++m) {
                        const float wh = __ldg(pwh + 32 * m);
                        const float wv = __ldg(pwv + 32 * m);
                        whp[m] = pk2(wh, wh);
                        wvp[m] = pk2(wv, wv);
                    }
                    pwh += Hsz; pwv += Hsz;
#pragma unroll
                    for (int g2 = 0; g2 < G2sz; ++g2) {
                        const ulonglong2 c = C0s[g2][k];   // LDS.128 broadcast
#pragma unroll
                        for (int m = 0; m < 4; ++m) {
                            a[g2][m] = fma2(c.x, whp[m], a[g2][m]);
                            a[g2][m] = fma2(c.y, wvp[m], a[g2][m]);
                        }
                    }
                }
            }
#pragma unroll
            for (int g2 = 0; g2 < G2sz; ++g2)
#pragma unroll
                for (int m = 0; m < 4; ++m)
                    RedS[g2][q][t4 + 32 * m] = a[g2][m];   // coalesced STS.64
            __syncthreads();   // s2

            // ---------------- layer 0 combine (one output per thread) ----------------
            {
                unsigned long long r0 = add2(RedS[cg][0][ct],  RedS[cg][1][ct]);
                unsigned long long r1 = add2(RedS[cg][2][ct],  RedS[cg][3][ct]);
                unsigned long long r2 = add2(RedS[cg][4][ct],  RedS[cg][5][ct]);
                unsigned long long r3 = add2(RedS[cg][6][ct],  RedS[cg][7][ct]);
                unsigned long long r4 = add2(RedS[cg][8][ct],  RedS[cg][9][ct]);
                unsigned long long r5 = add2(RedS[cg][10][ct], RedS[cg][11][ct]);
                unsigned long long r6 = add2(RedS[cg][12][ct], RedS[cg][13][ct]);
                unsigned long long r7 = add2(RedS[cg][14][ct], RedS[cg][15][ct]);
                const unsigned long long s =
                    add2(add2(add2(r0, r1), add2(r2, r3)),
                         add2(add2(r4, r5), add2(r6, r7)));
                float2 h = up2(s);
                // one-hot state term: at most two row-picks of WS0 per sample
                const int he = (j > 0) ? xbuf[cur][2 * cg][p - d] : -1;
                const int ho = (j > 0) ? xbuf[cur][2 * cg + 1][p - d] : -1;
                const int ve = (i > 0) ? xbuf[prv][2 * cg][p] : -1;
                const int vo = (i > 0) ? xbuf[prv][2 * cg + 1][p] : -1;
                if (he >= 0) h.x += WS0s[he * Hsz + ct];
                if (ve >= 0) h.x += WS0s[(2 + ve) * Hsz + ct];
                if (ho >= 0) h.y += WS0s[ho * Hsz + ct];
                if (vo >= 0) h.y += WS0s[(2 + vo) * Hsz + ct];
                h.x = eluf(h.x); h.y = eluf(h.y);
                const unsigned long long hu = pk2(h.x, h.y);
                C0s[cg][ct].x = hu;                                   // next-site carryH0
                H0sm[cg][ct] = hu;                                    // feeds WS1 matvec
                scrBase[((cg * Lsz + p) * 2 + 0) * Hsz + ct] = h;     // next-row carryV0
            }
            __syncthreads();   // s3

            // ---------------- layer 1 matvec ----------------
#pragma unroll
            for (int g2 = 0; g2 < G2sz; ++g2)
#pragma unroll
                for (int m = 0; m < 4; ++m) a[g2][m] = 0ull;
            {
                const float* pwh = WH1 + (size_t)kbase * Hsz + t4;
                const float* pwv = WV1 + (size_t)kbase * Hsz + t4;
                const float* pws = WS1 + (size_t)kbase * Hsz + t4;
#pragma unroll 4
                for (int kk = 0; kk < KQ; ++kk) {
                    const int k = kbase + kk;
                    unsigned long long whp[4], wvp[4], wsp[4];
#pragma unroll
                    for (int m = 0; m < 4; ++m) {
                        const float wh = __ldg(pwh + 32 * m);
                        const float wv = __ldg(pwv + 32 * m);
                        const float ws = __ldg(pws + 32 * m);
                        whp[m] = pk2(wh, wh);
                        wvp[m] = pk2(wv, wv);
                        wsp[m] = pk2(ws, ws);
                    }
                    pwh += Hsz; pwv += Hsz; pws += Hsz;
#pragma unroll
                    for (int g2 = 0; g2 < G2sz; ++g2) {
                        const ulonglong2 c = C1s[g2][k];
                        const unsigned long long h0u = H0sm[g2][k];
#pragma unroll
                        for (int m = 0; m < 4; ++m) {
                            a[g2][m] = fma2(c.x, whp[m], a[g2][m]);
                            a[g2][m] = fma2(c.y, wvp[m], a[g2][m]);
                            a[g2][m] = fma2(h0u, wsp[m], a[g2][m]);
                        }
                    }
                }
            }
#pragma unroll
            for (int g2 = 0; g2 < G2sz; ++g2)
#pragma unroll
                for (int m = 0; m < 4; ++m)
                    RedS[g2][q][t4 + 32 * m] = a[g2][m];
            __syncthreads();   // s4

            // ---------------- layer 1 combine + output dot ----------------
            {
                unsigned long long r0 = add2(RedS[cg][0][ct],  RedS[cg][1][ct]);
                unsigned long long r1 = add2(RedS[cg][2][ct],  RedS[cg][3][ct]);
                unsigned long long r2 = add2(RedS[cg][4][ct],  RedS[cg][5][ct]);
                unsigned long long r3 = add2(RedS[cg][6][ct],  RedS[cg][7][ct]);
                unsigned long long r4 = add2(RedS[cg][8][ct],  RedS[cg][9][ct]);
                unsigned long long r5 = add2(RedS[cg][10][ct], RedS[cg][11][ct]);
                unsigned long long r6 = add2(RedS[cg][12][ct], RedS[cg][13][ct]);
                unsigned long long r7 = add2(RedS[cg][14][ct], RedS[cg][15][ct]);
                const unsigned long long s =
                    add2(add2(add2(r0, r1), add2(r2, r3)),
                         add2(add2(r4, r5), add2(r6, r7)));
                float2 h = up2(s);
                h.x = eluf(h.x); h.y = eluf(h.y);
                const unsigned long long hu = pk2(h.x, h.y);
                C1s[cg][ct].x = hu;                                   // next-site carryH1
                scrBase[((cg * Lsz + p) * 2 + 1) * Hsz + ct] = h;     // next-row carryV1

                const float wof = WoutS[ct];
                unsigned long long pd = fma2(hu, pk2(wof, wof), 0ull);
#pragma unroll
                for (int off = 16; off > 0; off >>= 1)
                    pd = add2(pd, __shfl_down_sync(0xffffffffu, pd, off));
                if ((tid & 31) == 0) OutRedS[tid >> 5] = up2(pd);
            }
            __syncthreads();   // s5

            if (tid < Gsz) {
                const int g = tid;
                const int wb = 4 * (g >> 1);
                float c = boutS;
#pragma unroll
                for (int u = 0; u < 4; ++u) {
                    const float2 v = OutRedS[wb + u];
                    c += (g & 1) ? v.y : v.x;
                }
                // 0.5 * log_softmax([0, c]) picked by the observed spin
                const float sp = fmaxf(c, 0.f) + log1pf(__expf(-fabsf(c)));
                float lp = 0.5f * (((xbuf[cur][g][p] == 1) ? c : 0.f) - sp);
                if (!(lp == lp)) lp = -35.0f;   // nan_to_num semantics
                lpAcc += lp;
            }
        }
    }

    if (tid < Gsz) out[cta * Gsz + tid] = lpAcc;
}

extern "C" void kernel_launch(void* const* d_in, const int* in_sizes, int n_in,
                              void* d_out, int out_size) {
    const int*   x    = (const int*)d_in[0];
    const float* WH   = (const float*)d_in[1];
    const float* WV   = (const float*)d_in[2];
    const float* WS0  = (const float*)d_in[3];
    const float* WS1  = (const float*)d_in[4];
    const float* Wout = (const float*)d_in[5];
    const float* bo   = (const float*)d_in[6];
    float* out = (float*)d_out;
    rnn2d_kernel<<<NCTA, TPB>>>(x, WH, WV, WS0, WS1, Wout, bo, out);
}

// round 16
// speedup vs baseline: 1.6409x; 1.1398x over previous
#include <cuda_runtime.h>
#include <cstdint>

// Problem constants (fixed by the reference).
#define Bsz   1024
#define Lsz   32
#define Hsz   128
#define Gsz   8      // samples per CTA
#define G2sz  4      // sample pairs per CTA
#define NCTA  128    // Bsz / Gsz
#define TPB   512
#define NQ    16     // k-groups (warps)
#define KQ    8      // k-values per group

// Vertical-carry scratch: [cta][g2][lattice p][layer][t] as float2 (sample pair).
__device__ float2 g_scr[(size_t)NCTA * G2sz * Lsz * 2 * Hsz];

static __device__ __forceinline__ unsigned long long pk2(float x, float y) {
    unsigned long long r;
    asm("mov.b64 %0, {%1, %2};" : "=l"(r) : "f"(x), "f"(y));
    return r;
}
static __device__ __forceinline__ float2 up2(unsigned long long v) {
    float2 r;
    asm("mov.b64 {%0, %1}, %2;" : "=f"(r.x), "=f"(r.y) : "l"(v));
    return r;
}
// packed fp32x2 FMA / ADD (FFMA2 in SASS — PTX-only path on sm_103a)
static __device__ __forceinline__ unsigned long long fma2(unsigned long long a,
                                                          unsigned long long b,
                                                          unsigned long long c) {
    unsigned long long d;
    asm("fma.rn.f32x2 %0, %1, %2, %3;" : "=l"(d) : "l"(a), "l"(b), "l"(c));
    return d;
}
static __device__ __forceinline__ unsigned long long add2(unsigned long long a,
                                                          unsigned long long b) {
    unsigned long long d;
    asm("add.rn.f32x2 %0, %1, %2;" : "=l"(d) : "l"(a), "l"(b));
    return d;
}
static __device__ __forceinline__ float eluf(float v) {
    return v > 0.f ? v : (__expf(v) - 1.f);
}
// streaming (evict-first) global accesses for the carry scratch
static __device__ __forceinline__ float2 ldcs2(const float2* p) {
    float2 r;
    asm volatile("ld.global.cs.v2.f32 {%0,%1}, [%2];" : "=f"(r.x), "=f"(r.y) : "l"(p));
    return r;
}
static __device__ __forceinline__ void stcs2(float2* p, float2 v) {
    asm volatile("st.global.cs.v2.f32 [%0], {%1,%2};" :: "l"(p), "f"(v.x), "f"(v.y) : "memory");
}

__global__ void __launch_bounds__(TPB, 1)
rnn2d_kernel(const int* __restrict__ x,
             const float* __restrict__ WH,
             const float* __restrict__ WV,
             const float* __restrict__ WS0,
             const float* __restrict__ WS1,
             const float* __restrict__ Wout,
             const float* __restrict__ bout,
             float* __restrict__ out)
{
    // Carry operand arrays: .x = {carryH pair}, .y = {carryV pair} packed fp32x2.
    __shared__ ulonglong2 C0s[G2sz][Hsz];                 // layer-0 carries
    __shared__ ulonglong2 C1s[G2sz][Hsz];                 // layer-1 carries
    __shared__ unsigned long long H0sm[G2sz][Hsz];        // current-site h0 pairs
    __shared__ unsigned long long RedS[G2sz][NQ][Hsz];    // k-group partials (64 KB)
    __shared__ float2 LpS[G2sz][Lsz];                     // per-row log-prob pairs
    __shared__ float WS0s[4 * Hsz];
    __shared__ float WoutS[Hsz];
    __shared__ int   xbuf[2][Gsz][Lsz];                   // current / previous lattice rows
    __shared__ float boutS;

    const int tid = threadIdx.x;
    const int cta = blockIdx.x;

    // matvec role: warp q handles k in [kbase, kbase+KQ); thread owns outputs
    // {2t4, 2t4+1, 2t4+64, 2t4+65} so weight loads are coalesced float2 (LDG.64).
    const int t4    = tid & 31;
    const int q     = tid >> 5;          // warp id = k-group 0..15
    const int kbase = q * KQ;

    // combine role: one output (cg, ct) per thread
    const int ct = tid & 127;
    const int cg = tid >> 7;             // 0..3

    // staging role: group cg stages layer (cg>>1) for pair-base 2*(cg&1)
    const int stgL  = cg >> 1;
    const int stgPb = (cg & 1) * 2;

    for (int idx = tid; idx < 4 * Hsz; idx += TPB) WS0s[idx] = WS0[idx];
    for (int idx = tid; idx < Hsz; idx += TPB)     WoutS[idx] = Wout[idx];
    if (tid == 0) boutS = bout[0];

    // initial carries = 0
    C0s[cg][ct].x = 0ull; C0s[cg][ct].y = 0ull;
    C1s[cg][ct].x = 0ull; C1s[cg][ct].y = 0ull;

    const float* WH0 = WH;
    const float* WH1 = WH + Hsz * Hsz;
    const float* WV0 = WV;
    const float* WV1 = WV + Hsz * Hsz;

    float2* scrBase = g_scr + (size_t)cta * (G2sz * Lsz * 2 * Hsz);

    float lpAcc = 0.f;
    float2 vpref[2] = {{0.f, 0.f}, {0.f, 0.f}};
    __syncthreads();

    for (int i = 0; i < Lsz; ++i) {
        const int d = (i & 1) ? -1 : 1;               // boustrophedon direction
        const int cur = i & 1, prv = cur ^ 1;

        // stage the whole lattice row into smem (coalesced, once per row)
        if (tid < Gsz * Lsz) {
            const int g = tid >> 5, c = tid & 31;
            xbuf[cur][g][c] = x[((cta * Gsz + g) * Lsz + i) * Lsz + c];
        }

        // row-start staging of vertical carries for the first column
        {
            const int p0 = (d == 1) ? 0 : (Lsz - 1);
            if (i > 0) {
#pragma unroll
                for (int e = 0; e < 2; ++e)
                    vpref[e] = ldcs2(scrBase + (((stgPb + e) * Lsz + p0) * 2 + stgL) * Hsz + ct);
            } else {
                vpref[0] = make_float2(0.f, 0.f);
                vpref[1] = make_float2(0.f, 0.f);
            }
            ulonglong2* Cb = stgL ? &C1s[0][0] : &C0s[0][0];
#pragma unroll
            for (int e = 0; e < 2; ++e)
                Cb[(stgPb + e) * Hsz + ct].y = pk2(vpref[e].x, vpref[e].y);
        }
        __syncthreads();   // sR: row staged

        for (int j = 0; j < Lsz; ++j) {
            const int p = (d == 1) ? j : (Lsz - 1 - j);    // lattice column
            const bool lastInRow = (j == Lsz - 1);

            // prefetch next column's vertical carries (hidden under compute)
            if (!lastInRow) {
                const int pn = p + d;
                if (i > 0) {
#pragma unroll
                    for (int e = 0; e < 2; ++e)
                        vpref[e] = ldcs2(scrBase + (((stgPb + e) * Lsz + pn) * 2 + stgL) * Hsz + ct);
                } else {
                    vpref[0] = make_float2(0.f, 0.f);
                    vpref[1] = make_float2(0.f, 0.f);
                }
            }

            // ---------------- layer 0 matvec ----------------
            unsigned long long a[G2sz][4];
#pragma unroll
            for (int g2 = 0; g2 < G2sz; ++g2)
#pragma unroll
                for (int m = 0; m < 4; ++m) a[g2][m] = 0ull;
            {
                const float* pwh = WH0 + (size_t)kbase * Hsz + 2 * t4;
                const float* pwv = WV0 + (size_t)kbase * Hsz + 2 * t4;
#pragma unroll 4
                for (int kk = 0; kk < KQ; ++kk) {
                    const int k = kbase + kk;
                    const float2 whA = __ldg((const float2*)pwh);
                    const float2 whB = __ldg((const float2*)(pwh + 64));
                    const float2 wvA = __ldg((const float2*)pwv);
                    const float2 wvB = __ldg((const float2*)(pwv + 64));
                    pwh += Hsz; pwv += Hsz;
                    const unsigned long long wh[4] = {pk2(whA.x, whA.x), pk2(whA.y, whA.y),
                                                      pk2(whB.x, whB.x), pk2(whB.y, whB.y)};
                    const unsigned long long wv[4] = {pk2(wvA.x, wvA.x), pk2(wvA.y, wvA.y),
                                                      pk2(wvB.x, wvB.x), pk2(wvB.y, wvB.y)};
#pragma unroll
                    for (int g2 = 0; g2 < G2sz; ++g2) {
                        const ulonglong2 c = C0s[g2][k];   // LDS.128 broadcast
#pragma unroll
                        for (int m = 0; m < 4; ++m) {
                            a[g2][m] = fma2(c.x, wh[m], a[g2][m]);
                            a[g2][m] = fma2(c.y, wv[m], a[g2][m]);
                        }
                    }
                }
            }
#pragma unroll
            for (int g2 = 0; g2 < G2sz; ++g2) {
                ulonglong2 v0; v0.x = a[g2][0]; v0.y = a[g2][1];
                ulonglong2 v1; v1.x = a[g2][2]; v1.y = a[g2][3];
                *(ulonglong2*)&RedS[g2][q][2 * t4]      = v0;   // STS.128
                *(ulonglong2*)&RedS[g2][q][2 * t4 + 64] = v1;
            }
            __syncthreads();   // s2

            // ---------------- layer 0 combine (one output per thread) ----------------
            {
                unsigned long long r0 = add2(RedS[cg][0][ct],  RedS[cg][1][ct]);
                unsigned long long r1 = add2(RedS[cg][2][ct],  RedS[cg][3][ct]);
                unsigned long long r2 = add2(RedS[cg][4][ct],  RedS[cg][5][ct]);
                unsigned long long r3 = add2(RedS[cg][6][ct],  RedS[cg][7][ct]);
                unsigned long long r4 = add2(RedS[cg][8][ct],  RedS[cg][9][ct]);
                unsigned long long r5 = add2(RedS[cg][10][ct], RedS[cg][11][ct]);
                unsigned long long r6 = add2(RedS[cg][12][ct], RedS[cg][13][ct]);
                unsigned long long r7 = add2(RedS[cg][14][ct], RedS[cg][15][ct]);
                const unsigned long long s =
                    add2(add2(add2(r0, r1), add2(r2, r3)),
                         add2(add2(r4, r5), add2(r6, r7)));
                float2 h = up2(s);
                // one-hot state term: at most two row-picks of WS0 per sample
                const int he = (j > 0) ? xbuf[cur][2 * cg][p - d] : -1;
                const int ho = (j > 0) ? xbuf[cur][2 * cg + 1][p - d] : -1;
                const int ve = (i > 0) ? xbuf[prv][2 * cg][p] : -1;
                const int vo = (i > 0) ? xbuf[prv][2 * cg + 1][p] : -1;
                if (he >= 0) h.x += WS0s[he * Hsz + ct];
                if (ve >= 0) h.x += WS0s[(2 + ve) * Hsz + ct];
                if (ho >= 0) h.y += WS0s[ho * Hsz + ct];
                if (vo >= 0) h.y += WS0s[(2 + vo) * Hsz + ct];
                h.x = eluf(h.x); h.y = eluf(h.y);
                const unsigned long long hu = pk2(h.x, h.y);
                C0s[cg][ct].x = lastInRow ? 0ull : hu;                // next-site carryH0
                H0sm[cg][ct] = hu;                                    // feeds WS1 matvec
                stcs2(scrBase + ((cg * Lsz + p) * 2 + 0) * Hsz + ct, h); // next-row carryV0
            }
            __syncthreads();   // s3

            // ---------------- layer 1 matvec ----------------
#pragma unroll
            for (int g2 = 0; g2 < G2sz; ++g2)
#pragma unroll
                for (int m = 0; m < 4; ++m) a[g2][m] = 0ull;
            {
                const float* pwh = WH1 + (size_t)kbase * Hsz + 2 * t4;
                const float* pwv = WV1 + (size_t)kbase * Hsz + 2 * t4;
                const float* pws = WS1 + (size_t)kbase * Hsz + 2 * t4;
#pragma unroll 4
                for (int kk = 0; kk < KQ; ++kk) {
                    const int k = kbase + kk;
                    const float2 whA = __ldg((const float2*)pwh);
                    const float2 whB = __ldg((const float2*)(pwh + 64));
                    const float2 wvA = __ldg((const float2*)pwv);
                    const float2 wvB = __ldg((const float2*)(pwv + 64));
                    const float2 wsA = __ldg((const float2*)pws);
                    const float2 wsB = __ldg((const float2*)(pws + 64));
                    pwh += Hsz; pwv += Hsz; pws += Hsz;
                    const unsigned long long wh[4] = {pk2(whA.x, whA.x), pk2(whA.y, whA.y),
                                                      pk2(whB.x, whB.x), pk2(whB.y, whB.y)};
                    const unsigned long long wv[4] = {pk2(wvA.x, wvA.x), pk2(wvA.y, wvA.y),
                                                      pk2(wvB.x, wvB.x), pk2(wvB.y, wvB.y)};
                    const unsigned long long ws[4] = {pk2(wsA.x, wsA.x), pk2(wsA.y, wsA.y),
                                                      pk2(wsB.x, wsB.x), pk2(wsB.y, wsB.y)};
#pragma unroll
                    for (int g2 = 0; g2 < G2sz; ++g2) {
                        const ulonglong2 c = C1s[g2][k];
                        const unsigned long long h0u = H0sm[g2][k];
#pragma unroll
                        for (int m = 0; m < 4; ++m) {
                            a[g2][m] = fma2(c.x, wh[m], a[g2][m]);
                            a[g2][m] = fma2(c.y, wv[m], a[g2][m]);
                            a[g2][m] = fma2(h0u, ws[m], a[g2][m]);
                        }
                    }
                }
            }
#pragma unroll
            for (int g2 = 0; g2 < G2sz; ++g2) {
                ulonglong2 v0; v0.x = a[g2][0]; v0.y = a[g2][1];
                ulonglong2 v1; v1.x = a[g2][2]; v1.y = a[g2][3];
                *(ulonglong2*)&RedS[g2][q][2 * t4]      = v0;
                *(ulonglong2*)&RedS[g2][q][2 * t4 + 64] = v1;
            }
            __syncthreads();   // s4

            // ---------------- layer 1 combine + stage next site ----------------
            {
                unsigned long long r0 = add2(RedS[cg][0][ct],  RedS[cg][1][ct]);
                unsigned long long r1 = add2(RedS[cg][2][ct],  RedS[cg][3][ct]);
                unsigned long long r2 = add2(RedS[cg][4][ct],  RedS[cg][5][ct]);
                unsigned long long r3 = add2(RedS[cg][6][ct],  RedS[cg][7][ct]);
                unsigned long long r4 = add2(RedS[cg][8][ct],  RedS[cg][9][ct]);
                unsigned long long r5 = add2(RedS[cg][10][ct], RedS[cg][11][ct]);
                unsigned long long r6 = add2(RedS[cg][12][ct], RedS[cg][13][ct]);
                unsigned long long r7 = add2(RedS[cg][14][ct], RedS[cg][15][ct]);
                const unsigned long long s =
                    add2(add2(add2(r0, r1), add2(r2, r3)),
                         add2(add2(r4, r5), add2(r6, r7)));
                float2 h = up2(s);
                h.x = eluf(h.x); h.y = eluf(h.y);
                const unsigned long long hu = pk2(h.x, h.y);
                C1s[cg][ct].x = lastInRow ? 0ull : hu;                // next-site carryH1
                stcs2(scrBase + ((cg * Lsz + p) * 2 + 1) * Hsz + ct, h); // next-row carryV1 (+output head)
            }
            if (!lastInRow) {
                ulonglong2* Cb = stgL ? &C1s[0][0] : &C0s[0][0];
#pragma unroll
                for (int e = 0; e < 2; ++e)
                    Cb[(stgPb + e) * Hsz + ct].y = pk2(vpref[e].x, vpref[e].y);
            }
            __syncthreads();   // s5: end of site
        }

        // ---------------- row output phase: c = h1·Wout + b for all 32 sites ----------------
        {
#pragma unroll
            for (int u = 0; u < 8; ++u) {
                const int tau = q * 8 + u;          // task = (g2, p)
                const int g2r = tau >> 5;
                const int pr  = tau & 31;
                const float2* hp = scrBase + ((g2r * Lsz + pr) * 2 + 1) * Hsz;
                unsigned long long acc = 0ull;
#pragma unroll
                for (int m = 0; m < 4; ++m) {
                    const int tt = t4 + 32 * m;
                    const float2 hv = ldcs2(hp + tt);
                    const float w = WoutS[tt];
                    acc = fma2(pk2(hv.x, hv.y), pk2(w, w), acc);
                }
#pragma unroll
                for (int off = 16; off > 0; off >>= 1)
                    acc = add2(acc, __shfl_down_sync(0xffffffffu, acc, off));
                if (t4 == 0) {
                    const float2 cc = up2(acc);
                    const float cs[2] = {cc.x + boutS, cc.y + boutS};
                    float lpv[2];
#pragma unroll
                    for (int e = 0; e < 2; ++e) {
                        const float cv = cs[e];
                        // 0.5 * log_softmax([0, c]) picked by the observed spin
                        const float sp = fmaxf(cv, 0.f) + log1pf(__expf(-fabsf(cv)));
                        const int spin = xbuf[cur][2 * g2r + e][pr];
                        float lp = 0.5f * (((spin == 1) ? cv : 0.f) - sp);
                        if (!(lp == lp)) lp = -35.0f;   // nan_to_num semantics
                        lpv[e] = lp;
                    }
                    LpS[g2r][pr] = make_float2(lpv[0], lpv[1]);
                }
            }
        }
        __syncthreads();   // s6: LpS ready
        if (tid < Gsz) {
            const int g = tid;
#pragma unroll 8
            for (int pp = 0; pp < Lsz; ++pp) {
                const float2 v = LpS[g >> 1][pp];
                lpAcc += (g & 1) ? v.y : v.x;
            }
        }
    }

    if (tid < Gsz) out[cta * Gsz + tid] = lpAcc;
}

extern "C" void kernel_launch(void* const* d_in, const int* in_sizes, int n_in,
                              void* d_out, int out_size) {
    const int*   x    = (const int*)d_in[0];
    const float* WH   = (const float*)d_in[1];
    const float* WV   = (const float*)d_in[2];
    const float* WS0  = (const float*)d_in[3];
    const float* WS1  = (const float*)d_in[4];
    const float* Wout = (const float*)d_in[5];
    const float* bo   = (const float*)d_in[6];
    float* out = (float*)d_out;
    rnn2d_kernel<<<NCTA, TPB>>>(x, WH, WV, WS0, WS1, Wout, bo, out);
}

// round 17
// speedup vs baseline: 1.6717x; 1.0187x over previous
#include <cuda_runtime.h>
#include <cstdint>

// Problem constants (fixed by the reference).
#define Bsz   1024
#define Lsz   32
#define Hsz   128
#define Gsz   8      // samples per CTA
#define G2sz  4      // sample pairs per CTA
#define NCTA  128    // Bsz / Gsz
#define TPB   512
#define NQ2   8      // k-groups per layer (warps 0-7: layer1, 8-15: layer0)
#define KQ2   16     // k-values per group

// Vertical-carry scratch: [cta][g2][lattice p][layer][t] as float2 (sample pair).
__device__ float2 g_scr[(size_t)NCTA * G2sz * Lsz * 2 * Hsz];

static __device__ __forceinline__ unsigned long long pk2(float x, float y) {
    unsigned long long r;
    asm("mov.b64 %0, {%1, %2};" : "=l"(r) : "f"(x), "f"(y));
    return r;
}
static __device__ __forceinline__ float2 up2(unsigned long long v) {
    float2 r;
    asm("mov.b64 {%0, %1}, %2;" : "=f"(r.x), "=f"(r.y) : "l"(v));
    return r;
}
// packed fp32x2 FMA / ADD (FFMA2 in SASS — PTX-only path on sm_103a)
static __device__ __forceinline__ unsigned long long fma2(unsigned long long a,
                                                          unsigned long long b,
                                                          unsigned long long c) {
    unsigned long long d;
    asm("fma.rn.f32x2 %0, %1, %2, %3;" : "=l"(d) : "l"(a), "l"(b), "l"(c));
    return d;
}
static __device__ __forceinline__ unsigned long long add2(unsigned long long a,
                                                          unsigned long long b) {
    unsigned long long d;
    asm("add.rn.f32x2 %0, %1, %2;" : "=l"(d) : "l"(a), "l"(b));
    return d;
}
static __device__ __forceinline__ float eluf(float v) {
    return v > 0.f ? v : (__expf(v) - 1.f);
}
// streaming (evict-first) global accesses for the carry scratch
static __device__ __forceinline__ float2 ldcs2(const float2* p) {
    float2 r;
    asm volatile("ld.global.cs.v2.f32 {%0,%1}, [%2];" : "=f"(r.x), "=f"(r.y) : "l"(p));
    return r;
}
static __device__ __forceinline__ void stcs2(float2* p, float2 v) {
    asm volatile("st.global.cs.v2.f32 [%0], {%1,%2};" :: "l"(p), "f"(v.x), "f"(v.y) : "memory");
}

// layer-0 matvec slice: 2 weight matrices, carries from C (.x=carryH, .y=carryV)
static __device__ __forceinline__ void matvecL0(
    const float* __restrict__ WHb, const float* __restrict__ WVb,
    const ulonglong2 (*__restrict__ C)[Hsz],
    unsigned long long (*__restrict__ Red)[NQ2][Hsz],
    int kb, int qq, int t4)
{
    unsigned long long a[G2sz][4];
#pragma unroll
    for (int g2 = 0; g2 < G2sz; ++g2)
#pragma unroll
        for (int m = 0; m < 4; ++m) a[g2][m] = 0ull;
    const float* pwh = WHb + (size_t)kb * Hsz + 2 * t4;
    const float* pwv = WVb + (size_t)kb * Hsz + 2 * t4;
#pragma unroll 4
    for (int kk = 0; kk < KQ2; ++kk) {
        const int k = kb + kk;
        const float2 whA = __ldg((const float2*)pwh);
        const float2 whB = __ldg((const float2*)(pwh + 64));
        const float2 wvA = __ldg((const float2*)pwv);
        const float2 wvB = __ldg((const float2*)(pwv + 64));
        pwh += Hsz; pwv += Hsz;
        const unsigned long long wh[4] = {pk2(whA.x, whA.x), pk2(whA.y, whA.y),
                                          pk2(whB.x, whB.x), pk2(whB.y, whB.y)};
        const unsigned long long wv[4] = {pk2(wvA.x, wvA.x), pk2(wvA.y, wvA.y),
                                          pk2(wvB.x, wvB.x), pk2(wvB.y, wvB.y)};
#pragma unroll
        for (int g2 = 0; g2 < G2sz; ++g2) {
            const ulonglong2 c = C[g2][k];     // LDS.128 broadcast
#pragma unroll
            for (int m = 0; m < 4; ++m)
                a[g2][m] = fma2(c.y, wv[m], fma2(c.x, wh[m], a[g2][m]));
        }
    }
#pragma unroll
    for (int g2 = 0; g2 < G2sz; ++g2) {
        ulonglong2 v0; v0.x = a[g2][0]; v0.y = a[g2][1];
        ulonglong2 v1; v1.x = a[g2][2]; v1.y = a[g2][3];
        *(ulonglong2*)&Red[g2][qq][2 * t4]      = v0;   // STS.128
        *(ulonglong2*)&Red[g2][qq][2 * t4 + 64] = v1;
    }
}

// layer-1 matvec slice: 3 weight matrices, carries C1 + h0 from H0sm
static __device__ __forceinline__ void matvecL1(
    const float* __restrict__ WHb, const float* __restrict__ WVb,
    const float* __restrict__ WSb,
    const ulonglong2 (*__restrict__ C)[Hsz],
    const unsigned long long (*__restrict__ H0)[Hsz],
    unsigned long long (*__restrict__ Red)[NQ2][Hsz],
    int kb, int qq, int t4)
{
    unsigned long long a[G2sz][4];
#pragma unroll
    for (int g2 = 0; g2 < G2sz; ++g2)
#pragma unroll
        for (int m = 0; m < 4; ++m) a[g2][m] = 0ull;
    const float* pwh = WHb + (size_t)kb * Hsz + 2 * t4;
    const float* pwv = WVb + (size_t)kb * Hsz + 2 * t4;
    const float* pws = WSb + (size_t)kb * Hsz + 2 * t4;
#pragma unroll 4
    for (int kk = 0; kk < KQ2; ++kk) {
        const int k = kb + kk;
        const float2 whA = __ldg((const float2*)pwh);
        const float2 whB = __ldg((const float2*)(pwh + 64));
        const float2 wvA = __ldg((const float2*)pwv);
        const float2 wvB = __ldg((const float2*)(pwv + 64));
        const float2 wsA = __ldg((const float2*)pws);
        const float2 wsB = __ldg((const float2*)(pws + 64));
        pwh += Hsz; pwv += Hsz; pws += Hsz;
        const unsigned long long wh[4] = {pk2(whA.x, whA.x), pk2(whA.y, whA.y),
                                          pk2(whB.x, whB.x), pk2(whB.y, whB.y)};
        const unsigned long long wv[4] = {pk2(wvA.x, wvA.x), pk2(wvA.y, wvA.y),
                                          pk2(wvB.x, wvB.x), pk2(wvB.y, wvB.y)};
        const unsigned long long ws[4] = {pk2(wsA.x, wsA.x), pk2(wsA.y, wsA.y),
                                          pk2(wsB.x, wsB.x), pk2(wsB.y, wsB.y)};
#pragma unroll
        for (int g2 = 0; g2 < G2sz; ++g2) {
            const ulonglong2 c = C[g2][k];
            const unsigned long long h0u = H0[g2][k];
#pragma unroll
            for (int m = 0; m < 4; ++m)
                a[g2][m] = fma2(h0u, ws[m], fma2(c.y, wv[m], fma2(c.x, wh[m], a[g2][m])));
        }
    }
#pragma unroll
    for (int g2 = 0; g2 < G2sz; ++g2) {
        ulonglong2 v0; v0.x = a[g2][0]; v0.y = a[g2][1];
        ulonglong2 v1; v1.x = a[g2][2]; v1.y = a[g2][3];
        *(ulonglong2*)&Red[g2][qq][2 * t4]      = v0;
        *(ulonglong2*)&Red[g2][qq][2 * t4 + 64] = v1;
    }
}

#define RED8(R, cg, ct)                                                    \
    add2(add2(add2(R[cg][0][ct], R[cg][1][ct]),                            \
              add2(R[cg][2][ct], R[cg][3][ct])),                           \
         add2(add2(R[cg][4][ct], R[cg][5][ct]),                            \
              add2(R[cg][6][ct], R[cg][7][ct])))

__global__ void __launch_bounds__(TPB, 1)
rnn2d_kernel(const int* __restrict__ x,
             const float* __restrict__ WH,
             const float* __restrict__ WV,
             const float* __restrict__ WS0,
             const float* __restrict__ WS1,
             const float* __restrict__ Wout,
             const float* __restrict__ bout,
             float* __restrict__ out)
{
    __shared__ ulonglong2 C0s[G2sz][Hsz];                 // layer-0 carries
    __shared__ ulonglong2 C1s[G2sz][Hsz];                 // layer-1 carries
    __shared__ unsigned long long H0sm[G2sz][Hsz];        // h0 pairs feeding WS1
    __shared__ unsigned long long Red0[G2sz][NQ2][Hsz];   // layer-0 partials (32 KB)
    __shared__ unsigned long long Red1[G2sz][NQ2][Hsz];   // layer-1 partials (32 KB)
    __shared__ float2 LpS[G2sz][Lsz];                     // per-row log-prob pairs
    __shared__ float WS0s[4 * Hsz];
    __shared__ float WoutS[Hsz];
    __shared__ int   xbuf[2][Gsz][Lsz];
    __shared__ float boutS;

    const int tid = threadIdx.x;
    const int cta = blockIdx.x;

    const int t4   = tid & 31;
    const int q    = tid >> 5;           // warp id
    const bool isL1 = (q < NQ2);         // warps 0-7: layer1; 8-15: layer0
    const int kb   = (q & 7) * KQ2;
    const int qq   = q & 7;

    const int ct = tid & 127;            // combine output lane
    const int cg = tid >> 7;             // combine pair group 0..3
    const int stgL  = cg >> 1;           // staging: layer
    const int stgPb = (cg & 1) * 2;      // staging: pair base

    for (int idx = tid; idx < 4 * Hsz; idx += TPB) WS0s[idx] = WS0[idx];
    for (int idx = tid; idx < Hsz; idx += TPB)     WoutS[idx] = Wout[idx];
    if (tid == 0) boutS = bout[0];
    if (tid < Gsz * Lsz) {
        const int g = tid >> 5, c = tid & 31;
        xbuf[0][g][c] = x[((cta * Gsz + g) * Lsz + 0) * Lsz + c];
    }
    C0s[cg][ct].x = 0ull; C0s[cg][ct].y = 0ull;
    C1s[cg][ct].x = 0ull; C1s[cg][ct].y = 0ull;

    const float* WH0 = WH;
    const float* WH1 = WH + Hsz * Hsz;
    const float* WV0 = WV;
    const float* WV1 = WV + Hsz * Hsz;

    float2* scrBase = g_scr + (size_t)cta * (G2sz * Lsz * 2 * Hsz);
    __syncthreads();

    // ---------------- prologue: layer0 of site 0 ----------------
    if (!isL1) matvecL0(WH0, WV0, C0s, Red0, kb, qq, t4);
    __syncthreads();
    {
        float2 h = up2(RED8(Red0, cg, ct));   // state terms are zero at (0,0)
        h.x = eluf(h.x); h.y = eluf(h.y);
        const unsigned long long hu = pk2(h.x, h.y);
        C0s[cg][ct].x = hu;                   // carryH0 for site 1
        H0sm[cg][ct] = hu;
        stcs2(scrBase + ((cg * Lsz + 0) * 2 + 0) * Hsz + ct, h);
    }
    __syncthreads();

    float lpAcc = 0.f;
    float2 v0a = {0.f, 0.f}, v0b = {0.f, 0.f};   // layer-0 vertical prefetch (site s+2)
    float2 v1a = {0.f, 0.f}, v1b = {0.f, 0.f};   // layer-1 vertical prefetch (site s+1)

    for (int s = 0; s < Lsz * Lsz; ++s) {
        const int i = s >> 5;
        const int j = s & 31;
        const int d = (i & 1) ? -1 : 1;
        const int p = (d == 1) ? j : (Lsz - 1 - j);
        const bool hasN  = (s < Lsz * Lsz - 1);
        const bool hasN2 = (s < Lsz * Lsz - 2);

        // ---- prefetch vertical carries from scratch (consumed in phase2) ----
        if (stgL == 1) {
            // carryV1 for site s+1 (same row; row-start handled by direct forward)
            if (hasN && j < Lsz - 1) {
                if (i > 0) {
                    const int pc = p + d;
                    v1a = ldcs2(scrBase + (((stgPb)     * Lsz + pc) * 2 + 1) * Hsz + ct);
                    v1b = ldcs2(scrBase + (((stgPb + 1) * Lsz + pc) * 2 + 1) * Hsz + ct);
                } else {
                    v1a = make_float2(0.f, 0.f); v1b = make_float2(0.f, 0.f);
                }
            }
        } else {
            // carryV0 for site s+2 (j==Lsz-2 handled by direct forward)
            if (hasN2 && j != Lsz - 2) {
                int pc; bool ld;
                if (j <= Lsz - 3) { pc = p + 2 * d; ld = (i > 0); }
                else              { pc = p - d;     ld = true;    }  // j==31 -> (i+1, 1)
                if (ld) {
                    v0a = ldcs2(scrBase + (((stgPb)     * Lsz + pc) * 2 + 0) * Hsz + ct);
                    v0b = ldcs2(scrBase + (((stgPb + 1) * Lsz + pc) * 2 + 0) * Hsz + ct);
                } else {
                    v0a = make_float2(0.f, 0.f); v0b = make_float2(0.f, 0.f);
                }
            }
        }

        // ---------------- phase 1: both matvecs in parallel warp sets ----------------
        if (isL1)       matvecL1(WH1, WV1, WS1, C1s, H0sm, Red1, kb, qq, t4);
        else if (hasN)  matvecL0(WH0, WV0, C0s, Red0, kb, qq, t4);
        __syncthreads();   // b1

        // ---------------- phase 2: combine h1(s) and h0(s+1) ----------------
        {
            // h1(s)
            float2 h1 = up2(RED8(Red1, cg, ct));
            h1.x = eluf(h1.x); h1.y = eluf(h1.y);
            const unsigned long long h1u = pk2(h1.x, h1.y);
            C1s[cg][ct].x = (j == Lsz - 1) ? 0ull : h1u;          // carryH1 for s+1
            if (j == Lsz - 1 && hasN) C1s[cg][ct].y = h1u;        // row-start vertical = h1(s)
            stcs2(scrBase + ((cg * Lsz + p) * 2 + 1) * Hsz + ct, h1);

            if (hasN) {
                int in, jn, pn, dn;
                if (j < Lsz - 1) { in = i;     jn = j + 1; dn = d;  pn = p + d; }
                else             { in = i + 1; jn = 0;     dn = -d; pn = p;     }
                float2 h = up2(RED8(Red0, cg, ct));
                const int he = (jn > 0) ? xbuf[in & 1][2 * cg][pn - dn] : -1;
                const int ho = (jn > 0) ? xbuf[in & 1][2 * cg + 1][pn - dn] : -1;
                const int ve = (in > 0) ? xbuf[(in & 1) ^ 1][2 * cg][pn] : -1;
                const int vo = (in > 0) ? xbuf[(in & 1) ^ 1][2 * cg + 1][pn] : -1;
                if (he >= 0) h.x += WS0s[he * Hsz + ct];
                if (ve >= 0) h.x += WS0s[(2 + ve) * Hsz + ct];
                if (ho >= 0) h.y += WS0s[ho * Hsz + ct];
                if (vo >= 0) h.y += WS0s[(2 + vo) * Hsz + ct];
                h.x = eluf(h.x); h.y = eluf(h.y);
                const unsigned long long h0u = pk2(h.x, h.y);
                C0s[cg][ct].x = (jn == Lsz - 1) ? 0ull : h0u;     // carryH0 for s+2
                if (j == Lsz - 2 && hasN2) C0s[cg][ct].y = h0u;   // s+2 row-start vertical
                H0sm[cg][ct] = h0u;
                stcs2(scrBase + ((cg * Lsz + pn) * 2 + 0) * Hsz + ct, h);
            }

            // staging-thread vertical-carry writes (disjoint from direct rules above)
            if (stgL == 1) {
                if (hasN && j < Lsz - 1) {
                    C1s[stgPb][ct].y     = pk2(v1a.x, v1a.y);
                    C1s[stgPb + 1][ct].y = pk2(v1b.x, v1b.y);
                }
            } else {
                if (hasN2 && j != Lsz - 2) {
                    C0s[stgPb][ct].y     = pk2(v0a.x, v0a.y);
                    C0s[stgPb + 1][ct].y = pk2(v0b.x, v0b.y);
                }
            }
        }
        __syncthreads();   // b2

        // ---------------- row output phase (once per row) ----------------
        if (j == Lsz - 1) {
#pragma unroll
            for (int u = 0; u < 8; ++u) {
                const int tau = q * 8 + u;          // task = (g2, p)
                const int g2r = tau >> 5;
                const int pr  = tau & 31;
                const float2* hp = scrBase + ((g2r * Lsz + pr) * 2 + 1) * Hsz;
                unsigned long long acc = 0ull;
#pragma unroll
                for (int m = 0; m < 4; ++m) {
                    const int tt = t4 + 32 * m;
                    const float2 hv = ldcs2(hp + tt);
                    const float w = WoutS[tt];
                    acc = fma2(pk2(hv.x, hv.y), pk2(w, w), acc);
                }
#pragma unroll
                for (int off = 16; off > 0; off >>= 1)
                    acc = add2(acc, __shfl_down_sync(0xffffffffu, acc, off));
                if (t4 == 0) {
                    const float2 cc = up2(acc);
                    const float cs[2] = {cc.x + boutS, cc.y + boutS};
                    float lpv[2];
#pragma unroll
                    for (int e = 0; e < 2; ++e) {
                        const float cv = cs[e];
                        const float sp = fmaxf(cv, 0.f) + log1pf(__expf(-fabsf(cv)));
                        const int spin = xbuf[i & 1][2 * g2r + e][pr];
                        float lp = 0.5f * (((spin == 1) ? cv : 0.f) - sp);
                        if (!(lp == lp)) lp = -35.0f;   // nan_to_num semantics
                        lpv[e] = lp;
                    }
                    LpS[g2r][pr] = make_float2(lpv[0], lpv[1]);
                }
            }
            // stage next row's lattice values (first needed in phase2 of step s+1)
            if (i < Lsz - 1 && tid < Gsz * Lsz) {
                const int g = tid >> 5, c = tid & 31;
                xbuf[(i + 1) & 1][g][c] = x[((cta * Gsz + g) * Lsz + (i + 1)) * Lsz + c];
            }
            __syncthreads();   // b3 (amortized: once per 32 sites)
            if (tid < Gsz) {
                const int g = tid;
#pragma unroll 8
                for (int pp = 0; pp < Lsz; ++pp) {
                    const float2 v = LpS[g >> 1][pp];
                    lpAcc += (g & 1) ? v.y : v.x;
                }
            }
        }
    }

    if (tid < Gsz) out[cta * Gsz + tid] = lpAcc;
}

extern "C" void kernel_launch(void* const* d_in, const int* in_sizes, int n_in,
                              void* d_out, int out_size) {
    const int*   x    = (const int*)d_in[0];
    const float* WH   = (const float*)d_in[1];
    const float* WV   = (const float*)d_in[2];
    const float* WS0  = (const float*)d_in[3];
    const float* WS1  = (const float*)d_in[4];
    const float* Wout = (const float*)d_in[5];
    const float* bo   = (const float*)d_in[6];
    float* out = (float*)d_out;
    rnn2d_kernel<<<NCTA, TPB>>>(x, WH, WV, WS0, WS1, Wout, bo, out);
}